// round 15
// baseline (speedup 1.0000x reference)
#include <cuda_runtime.h>
#include <cuda_bf16.h>
#include <math.h>
#include <stdint.h>

// Problem constants
#define N_TOKENS    16384
#define MODEL_DIM   2048
#define NUM_EXPERTS 64
#define TOPK        2
#define NK          (N_TOKENS * TOPK)      // 32768

#define BT    128                          // tokens per CTA
#define KSPLIT 2
#define KHALF (MODEL_DIM / KSPLIT)         // 1024
#define KC    64                           // K elements per chunk
#define NCHUNK (KHALF / KC)                // 16 chunks per CTA
#define NGATE (N_TOKENS / BT * KSPLIT)     // 256 gate CTAs
#define HBLK  (N_TOKENS / BT)              // 128 hist chunks
#define CHUNK (BT * TOPK)                  // 256 slots per hist chunk

// Output layout (concatenated float32, reference return order)
#define OFF_TOKEN  0
#define OFF_REV    (NK)
#define OFF_CW     (2 * NK)
#define OFF_SPLITS (3 * NK)
#define OFF_PROBS  (3 * NK + NUM_EXPERTS)

// Stage layout inside dynamic SMEM (per stage, 1024B aligned)
#define A_HI_OFF   0
#define A_LO_OFF   16384
#define B_HI_OFF   32768
#define B_LO_OFF   40960
#define STAGE_BYTES 49152                   // 48KB
#define SMEM_DYN   (1024 + 2 * STAGE_BYTES) // 99328 -> 2 CTAs/SM

// Scratch globals (no allocation allowed)
__device__ int g_flat_idx[NK];
__device__ int g_hist[HBLK][NUM_EXPERTS];
__device__ int g_offset[HBLK][NUM_EXPERTS];
__device__ __align__(16) float g_part[KSPLIT][N_TOKENS * NUM_EXPERTS]; // 8MB
__device__ __align__(16) __nv_bfloat16 g_Whi[NUM_EXPERTS * MODEL_DIM];
__device__ __align__(16) __nv_bfloat16 g_Wlo[NUM_EXPERTS * MODEL_DIM];

// ---------------------------------------------------------------------------
// Helpers (sm_80-compatible PTX only)
// ---------------------------------------------------------------------------
#define SMEM_SWIZZLE_128B(o) ((o) ^ (((o) >> 3) & 0x70u))

__device__ __forceinline__ uint32_t smem_to_u32(const void* p) {
    uint32_t a;
    asm("{ .reg .u64 t; cvta.to.shared.u64 t, %1; cvt.u32.u64 %0, t; }"
        : "=r"(a) : "l"(p));
    return a;
}

__device__ __forceinline__ void ldm_x4(uint32_t* r, uint32_t addr) {
    asm volatile("ldmatrix.sync.aligned.m8n8.x4.shared.b16 {%0,%1,%2,%3}, [%4];"
                 : "=r"(r[0]), "=r"(r[1]), "=r"(r[2]), "=r"(r[3]) : "r"(addr));
}

__device__ __forceinline__ void mma16816(float* c, const uint32_t* a,
                                         uint32_t b0, uint32_t b1) {
    asm volatile(
        "mma.sync.aligned.m16n8k16.row.col.f32.bf16.bf16.f32 "
        "{%0,%1,%2,%3}, {%4,%5,%6,%7}, {%8,%9}, {%0,%1,%2,%3};"
        : "+f"(c[0]), "+f"(c[1]), "+f"(c[2]), "+f"(c[3])
        : "r"(a[0]), "r"(a[1]), "r"(a[2]), "r"(a[3]), "r"(b0), "r"(b1));
}

// split one fp32 pair into bf16x2 hi and residual bf16x2 lo (x0 in low half)
__device__ __forceinline__ void cvt_pair(float x0, float x1,
                                         uint32_t& hi2, uint32_t& lo2) {
    asm("cvt.rn.bf16x2.f32 %0, %1, %2;" : "=r"(hi2) : "f"(x1), "f"(x0));
    float h0 = __uint_as_float(hi2 << 16);
    float h1 = __uint_as_float(hi2 & 0xffff0000u);
    float r0 = x0 - h0;
    float r1 = x1 - h1;
    asm("cvt.rn.bf16x2.f32 %0, %1, %2;" : "=r"(lo2) : "f"(r1), "f"(r0));
}

__device__ __forceinline__ void sts64(uint32_t addr, uint32_t a, uint32_t b) {
    asm volatile("st.shared.v2.b32 [%0], {%1, %2};"
                 :: "r"(addr), "r"(a), "r"(b) : "memory");
}

#define CP_ASYNC16(dst, src) \
    asm volatile("cp.async.cg.shared.global [%0], [%1], 16;" \
                 :: "r"(dst), "l"(src) : "memory")
#define CP_COMMIT() asm volatile("cp.async.commit_group;" ::: "memory")
#define CP_WAIT0()  asm volatile("cp.async.wait_group 0;" ::: "memory")

// ---------------------------------------------------------------------------
// Kernel 0: convert W fp32 -> bf16 hi/lo; zero g_hist
// ---------------------------------------------------------------------------
__global__ __launch_bounds__(256) void wconv_kernel(const float* __restrict__ W)
{
    int idx = blockIdx.x * 256 + threadIdx.x;      // 0 .. 32767
    float4 v = *(const float4*)(W + (size_t)idx * 4);
    uint32_t h0, l0, h1, l1;
    cvt_pair(v.x, v.y, h0, l0);
    cvt_pair(v.z, v.w, h1, l1);
    ((uint2*)g_Whi)[idx] = make_uint2(h0, h1);
    ((uint2*)g_Wlo)[idx] = make_uint2(l0, l1);
    if (idx < HBLK * NUM_EXPERTS) ((int*)g_hist)[idx] = 0;
}

// ---------------------------------------------------------------------------
// Kernel 1: HMMA split-bf16 gate GEMM, K-split x2 -> fp32 partials in gmem
// 256 threads, 8 warps (32x32 tiles), 2 CTAs/SM, ONE sync per chunk.
// ---------------------------------------------------------------------------
__global__ __launch_bounds__(256, 2) void gate_kernel(
    const float* __restrict__ X)    // [N_TOKENS, MODEL_DIM]
{
    extern __shared__ char dsm[];

    const int tid  = threadIdx.x;
    const int lane = tid & 31;
    const int w    = tid >> 5;
    const int b    = blockIdx.x >> 1;
    const int ks   = blockIdx.x & 1;
    const int t0   = b * BT;
    const int kbase = ks * KHALF;

    uint32_t smem_raw = smem_to_u32(dsm);
    const uint32_t tile0 = (smem_raw + 1023) & ~1023u;

    // Warp tile: 32 tokens x 32 experts
    const int wm = (w & 3) * 32;        // token rows
    const int wn = (w >> 2) * 32;       // expert cols

    const uint32_t a_row  = (uint32_t)(lane & 15);
    const uint32_t a_koff = (uint32_t)((lane >> 4) << 4);
    const uint32_t b_row  = (uint32_t)((lane & 7) + ((lane & 16) ? 8 : 0));
    const uint32_t b_koff = (uint32_t)((lane & 8) ? 16 : 0);

    float acc[2][4][4];
#pragma unroll
    for (int mi = 0; mi < 2; mi++)
#pragma unroll
        for (int j = 0; j < 4; j++)
#pragma unroll
            for (int q = 0; q < 4; q++) acc[mi][j][q] = 0.0f;

    // A prefetch registers: 128 rows x 16 float4 / 256 thr = 8 each
    float4 pa[8];
    const int brow = tid >> 3;          // B: 0..31 (x2 via l)
    const int bu   = tid & 7;

    // prologue: LDG A(0); cp.async B(0) into stage 0
    {
        const int k0 = kbase;
#pragma unroll
        for (int l = 0; l < 8; l++) {
            int i = l * 256 + tid;
            int row = i >> 4, q = i & 15;
            pa[l] = *(const float4*)(X + (size_t)(t0 + row) * MODEL_DIM + k0 + q * 4);
        }
#pragma unroll
        for (int l = 0; l < 2; l++) {
            int row = brow + l * 32;
            uint32_t off = SMEM_SWIZZLE_128B((uint32_t)(row * 128 + bu * 16));
            CP_ASYNC16(tile0 + B_HI_OFF + off,
                       (const char*)g_Whi + ((size_t)row * MODEL_DIM + k0) * 2 + bu * 16);
            CP_ASYNC16(tile0 + B_LO_OFF + off,
                       (const char*)g_Wlo + ((size_t)row * MODEL_DIM + k0) * 2 + bu * 16);
        }
        CP_COMMIT();
    }

    for (int c = 0; c < NCHUNK; c++) {
        const uint32_t sb  = tile0 + (uint32_t)(c & 1) * STAGE_BYTES;
        const uint32_t sbn = tile0 + (uint32_t)((c + 1) & 1) * STAGE_BYTES;

        // convert + store prefetched A chunk c into its stage
        // (safe vs other warps' MMA(c-2) on this stage: guaranteed done by sync(c-1))
#pragma unroll
        for (int l = 0; l < 8; l++) {
            int i = l * 256 + tid;
            int row = i >> 4, q = i & 15;
            uint32_t h0, l0v, h1, l1v;
            cvt_pair(pa[l].x, pa[l].y, h0, l0v);
            cvt_pair(pa[l].z, pa[l].w, h1, l1v);
            uint32_t off = SMEM_SWIZZLE_128B((uint32_t)(row * 128 + q * 8));
            sts64(sb + A_HI_OFF + off, h0, h1);
            sts64(sb + A_LO_OFF + off, l0v, l1v);
        }

        // LDG A(c+1) into regs (lands during MMA below)
        if (c + 1 < NCHUNK) {
            const int k0 = kbase + (c + 1) * KC;
#pragma unroll
            for (int l = 0; l < 8; l++) {
                int i = l * 256 + tid;
                int row = i >> 4, q = i & 15;
                pa[l] = *(const float4*)(X + (size_t)(t0 + row) * MODEL_DIM + k0 + q * 4);
            }
        }

        CP_WAIT0();          // B(c) landed
        __syncthreads();     // single sync: A(c)/B(c) visible; all MMA(c-1) done

        // cp.async B(c+1) into the opposite stage (safe post-sync: MMA(c-1) done)
        if (c + 1 < NCHUNK) {
            const int k0 = kbase + (c + 1) * KC;
#pragma unroll
            for (int l = 0; l < 2; l++) {
                int row = brow + l * 32;
                uint32_t off = SMEM_SWIZZLE_128B((uint32_t)(row * 128 + bu * 16));
                CP_ASYNC16(sbn + B_HI_OFF + off,
                           (const char*)g_Whi + ((size_t)row * MODEL_DIM + k0) * 2 + bu * 16);
                CP_ASYNC16(sbn + B_LO_OFF + off,
                           (const char*)g_Wlo + ((size_t)row * MODEL_DIM + k0) * 2 + bu * 16);
            }
            CP_COMMIT();
        }

        // compute: 4 k-steps of k16 over this chunk; bi serialized (reg pressure)
#pragma unroll
        for (int kk = 0; kk < 4; kk++) {
            uint32_t ah[2][4], al[2][4];
#pragma unroll
            for (int mi = 0; mi < 2; mi++) {
                uint32_t ro = (uint32_t)((wm + 16 * mi + a_row) * 128) + kk * 32 + a_koff;
                uint32_t sw = SMEM_SWIZZLE_128B(ro);
                ldm_x4(ah[mi], sb + A_HI_OFF + sw);
                ldm_x4(al[mi], sb + A_LO_OFF + sw);
            }
#pragma unroll
            for (int bi = 0; bi < 2; bi++) {
                uint32_t bhf[4], blf[4];
                uint32_t ro = (uint32_t)((wn + 16 * bi + b_row) * 128) + kk * 32 + b_koff;
                uint32_t sw = SMEM_SWIZZLE_128B(ro);
                ldm_x4(bhf, sb + B_HI_OFF + sw);
                ldm_x4(blf, sb + B_LO_OFF + sw);
#pragma unroll
                for (int mi = 0; mi < 2; mi++) {
#pragma unroll
                    for (int jj = 0; jj < 2; jj++) {
                        float* a = acc[mi][bi * 2 + jj];
                        mma16816(a, ah[mi], bhf[jj * 2], bhf[jj * 2 + 1]);
                        mma16816(a, ah[mi], blf[jj * 2], blf[jj * 2 + 1]);
                        mma16816(a, al[mi], bhf[jj * 2], bhf[jj * 2 + 1]);
                    }
                }
            }
        }
        // NO trailing sync: next chunk's STS targets the other stage and is
        // protected by the leading sync of the next iteration.
    }

    // Write fp32 partial logits to gmem
    float* gp = g_part[ks];
#pragma unroll
    for (int mi = 0; mi < 2; mi++) {
        int r0 = wm + 16 * mi + (lane >> 2);
#pragma unroll
        for (int j = 0; j < 4; j++) {
            int col = wn + j * 8 + 2 * (lane & 3);
            *(float2*)(gp + (size_t)(t0 + r0) * NUM_EXPERTS + col) =
                make_float2(acc[mi][j][0], acc[mi][j][1]);
            *(float2*)(gp + (size_t)(t0 + r0 + 8) * NUM_EXPERTS + col) =
                make_float2(acc[mi][j][2], acc[mi][j][3]);
        }
    }
}

// ---------------------------------------------------------------------------
// Kernel 2: warp-per-token: sum partials + softmax + top-2 + combine + hist
// 1024 blocks x 512 threads (16 warps = 16 tokens per block)
// ---------------------------------------------------------------------------
__global__ __launch_bounds__(512) void finish_kernel(float* __restrict__ out)
{
    const int tid  = threadIdx.x;
    const int lane = tid & 31;
    const int w    = tid >> 5;
    const int token = blockIdx.x * 16 + w;

    const float* p0 = g_part[0] + (size_t)token * NUM_EXPERTS;
    const float* p1 = g_part[1] + (size_t)token * NUM_EXPERTS;
    float v0 = p0[lane]      + p1[lane];
    float v1 = p0[lane + 32] + p1[lane + 32];

    // warp max -> m1
    float m = fmaxf(v0, v1);
#pragma unroll
    for (int off = 16; off > 0; off >>= 1)
        m = fmaxf(m, __shfl_xor_sync(0xffffffffu, m, off));
    const float m1 = m;

    // e1 = lowest index attaining m1 (indices 0..31 = v0 lanes, 32..63 = v1)
    unsigned bb0 = __ballot_sync(0xffffffffu, v0 == m1);
    unsigned bb1 = __ballot_sync(0xffffffffu, v1 == m1);
    const int e1 = bb0 ? (__ffs(bb0) - 1) : (32 + __ffs(bb1) - 1);

    // second max excluding e1
    float u0 = (lane == e1)      ? -INFINITY : v0;
    float u1 = (lane + 32 == e1) ? -INFINITY : v1;
    float m2 = fmaxf(u0, u1);
#pragma unroll
    for (int off = 16; off > 0; off >>= 1)
        m2 = fmaxf(m2, __shfl_xor_sync(0xffffffffu, m2, off));
    bb0 = __ballot_sync(0xffffffffu, u0 == m2);
    bb1 = __ballot_sync(0xffffffffu, u1 == m2);
    const int e2 = bb0 ? (__ffs(bb0) - 1) : (32 + __ffs(bb1) - 1);

    // softmax over 64 logits
    float ex0 = expf(v0 - m1);
    float ex1 = expf(v1 - m1);
    float s = ex0 + ex1;
#pragma unroll
    for (int off = 16; off > 0; off >>= 1)
        s += __shfl_xor_sync(0xffffffffu, s, off);
    const float inv = 1.0f / s;

    out[OFF_PROBS + (size_t)token * NUM_EXPERTS + lane]      = ex0 * inv;
    out[OFF_PROBS + (size_t)token * NUM_EXPERTS + lane + 32] = ex1 * inv;

    if (lane == 0) {
        float p1v = inv;                    // exp(m1-m1)*inv
        float p2v = expf(m2 - m1) * inv;
        float r  = expf(p2v - p1v);         // combine = softmax([p1,p2])
        float c1 = 1.0f / (1.0f + r);
        float c2 = r * c1;

        int gi = 2 * token;
        g_flat_idx[gi]     = e1;
        g_flat_idx[gi + 1] = e2;
        out[OFF_CW + gi]     = c1;
        out[OFF_CW + gi + 1] = c2;

        atomicAdd(&g_hist[token >> 7][e1], 1);
        atomicAdd(&g_hist[token >> 7][e2], 1);
    }
}

// ---------------------------------------------------------------------------
// Kernel 3: per-expert chunk-prefix + expert bases + input_splits
// Parallel: 256 threads = 64 experts x 4 segments of 32 chunks.
// Chain length 32 (was 128); offset writes coalesced across experts.
// ---------------------------------------------------------------------------
__global__ __launch_bounds__(256) void prefix_kernel(float* __restrict__ out)
{
    __shared__ int sh[HBLK * NUM_EXPERTS];     // 32KB
    __shared__ int seg[4][NUM_EXPERTS];        // per-segment totals
    __shared__ int segoff[4][NUM_EXPERTS];     // exclusive within expert
    __shared__ int s_cnt[NUM_EXPERTS];
    __shared__ int s_base[NUM_EXPERTS];
    const int tid = threadIdx.x;
    const int e   = tid & 63;
    const int s   = tid >> 6;                  // 0..3

    // stage full histogram (coalesced, 8 int4 per thread)
    {
        const int4* src = (const int4*)g_hist;
        int4* dst = (int4*)sh;
#pragma unroll
        for (int l = 0; l < 8; l++) dst[l * 256 + tid] = src[l * 256 + tid];
    }
    __syncthreads();

    // per-(expert, segment) sum over 32 chunks
    {
        int run = 0;
#pragma unroll 8
        for (int c = s * 32; c < s * 32 + 32; c++) run += sh[c * NUM_EXPERTS + e];
        seg[s][e] = run;
    }
    __syncthreads();

    // stitch segments + total count per expert (64 threads, chain 4)
    if (tid < NUM_EXPERTS) {
        int a0 = seg[0][tid], a1 = seg[1][tid], a2 = seg[2][tid], a3 = seg[3][tid];
        segoff[0][tid] = 0;
        segoff[1][tid] = a0;
        segoff[2][tid] = a0 + a1;
        segoff[3][tid] = a0 + a1 + a2;
        s_cnt[tid] = a0 + a1 + a2 + a3;
        out[OFF_SPLITS + tid] = (float)(a0 + a1 + a2 + a3);
    }
    __syncthreads();
    if (tid == 0) {
        int base = 0;
#pragma unroll
        for (int i = 0; i < NUM_EXPERTS; i++) { s_base[i] = base; base += s_cnt[i]; }
    }
    __syncthreads();

    // write g_offset: each thread covers its segment's 32 chunks.
    // consecutive e across lanes -> coalesced 128B stores per chunk row
    {
        int run = s_base[e] + segoff[s][e];
#pragma unroll 8
        for (int c = s * 32; c < s * 32 + 32; c++) {
            g_offset[c][e] = run;
            run += sh[c * NUM_EXPERTS + e];
        }
    }
}

// ---------------------------------------------------------------------------
// Kernel 4: stable scatter via match_any + per-warp histograms
// 128 blocks x 256 threads (8 warps), chunk = 256 slots
// ---------------------------------------------------------------------------
__global__ __launch_bounds__(CHUNK) void scatter_kernel(float* __restrict__ out)
{
    __shared__ int whist[8][NUM_EXPERTS];
    const int tid  = threadIdx.x;
    const int lane = tid & 31;
    const int w    = tid >> 5;
    const int b    = blockIdx.x;
    const int gi   = b * CHUNK + tid;

    for (int i = tid; i < 8 * NUM_EXPERTS; i += CHUNK) ((int*)whist)[i] = 0;
    __syncthreads();

    const int me = g_flat_idx[gi];
    unsigned mask = __match_any_sync(0xffffffffu, me);
    int before = __popc(mask & ((1u << lane) - 1u));
    if (before == 0) whist[w][me] = __popc(mask);   // lowest matching lane = leader
    __syncthreads();

    int r = before;
#pragma unroll
    for (int ww = 0; ww < 8; ww++)
        if (ww < w) r += whist[ww][me];

    const int pos = g_offset[b][me] + r;
    out[OFF_TOKEN + pos] = (float)(gi >> 1);   // token index
    out[OFF_REV + gi]    = (float)pos;         // reversed ordering
}

// ---------------------------------------------------------------------------
extern "C" void kernel_launch(void* const* d_in, const int* in_sizes, int n_in,
                              void* d_out, int out_size)
{
    const float* X = (const float*)d_in[0];   // inputs [16384, 2048]
    const float* W = (const float*)d_in[1];   // wg_weight [64, 2048]
    float* out = (float*)d_out;

    cudaFuncSetAttribute(gate_kernel,
                         cudaFuncAttributeMaxDynamicSharedMemorySize, SMEM_DYN);

    wconv_kernel<<<128, 256>>>(W);
    gate_kernel<<<NGATE, 256, SMEM_DYN>>>(X);
    finish_kernel<<<N_TOKENS / 16, 512>>>(out);
    prefix_kernel<<<1, 256>>>(out);
    scatter_kernel<<<HBLK, CHUNK>>>(out);
}

// round 17
// speedup vs baseline: 1.0734x; 1.0734x over previous
#include <cuda_runtime.h>
#include <cuda_bf16.h>
#include <math.h>
#include <stdint.h>

// Problem constants
#define N_TOKENS    16384
#define MODEL_DIM   2048
#define NUM_EXPERTS 64
#define TOPK        2
#define NK          (N_TOKENS * TOPK)      // 32768

#define BT    128                          // tokens per CTA
#define KSPLIT 2
#define KHALF (MODEL_DIM / KSPLIT)         // 1024
#define KC    64                           // K elements per chunk
#define NCHUNK (KHALF / KC)                // 16 chunks per CTA
#define NGATE (N_TOKENS / BT * KSPLIT)     // 256 gate CTAs
#define HBLK  (N_TOKENS / BT)              // 128 hist chunks
#define CHUNK (BT * TOPK)                  // 256 slots per hist chunk

// Output layout (concatenated float32, reference return order)
#define OFF_TOKEN  0
#define OFF_REV    (NK)
#define OFF_CW     (2 * NK)
#define OFF_SPLITS (3 * NK)
#define OFF_PROBS  (3 * NK + NUM_EXPERTS)

// Stage layout inside dynamic SMEM (per stage, 1024B aligned)
#define A_HI_OFF   0
#define A_LO_OFF   16384
#define B_HI_OFF   32768
#define B_LO_OFF   40960
#define STAGE_BYTES 49152                   // 48KB
#define SMEM_DYN   (1024 + 2 * STAGE_BYTES) // 99328 -> 2 CTAs/SM

// Scratch globals (no allocation allowed)
__device__ int g_flat_idx[NK];
__device__ int g_hist[HBLK][NUM_EXPERTS];
__device__ __align__(16) float g_part[KSPLIT][N_TOKENS * NUM_EXPERTS]; // 8MB
__device__ __align__(16) __nv_bfloat16 g_Whi[NUM_EXPERTS * MODEL_DIM];
__device__ __align__(16) __nv_bfloat16 g_Wlo[NUM_EXPERTS * MODEL_DIM];

// ---------------------------------------------------------------------------
// Helpers (sm_80-compatible PTX only)
// ---------------------------------------------------------------------------
#define SMEM_SWIZZLE_128B(o) ((o) ^ (((o) >> 3) & 0x70u))

__device__ __forceinline__ uint32_t smem_to_u32(const void* p) {
    uint32_t a;
    asm("{ .reg .u64 t; cvta.to.shared.u64 t, %1; cvt.u32.u64 %0, t; }"
        : "=r"(a) : "l"(p));
    return a;
}

__device__ __forceinline__ void ldm_x4(uint32_t* r, uint32_t addr) {
    asm volatile("ldmatrix.sync.aligned.m8n8.x4.shared.b16 {%0,%1,%2,%3}, [%4];"
                 : "=r"(r[0]), "=r"(r[1]), "=r"(r[2]), "=r"(r[3]) : "r"(addr));
}

__device__ __forceinline__ void mma16816(float* c, const uint32_t* a,
                                         uint32_t b0, uint32_t b1) {
    asm volatile(
        "mma.sync.aligned.m16n8k16.row.col.f32.bf16.bf16.f32 "
        "{%0,%1,%2,%3}, {%4,%5,%6,%7}, {%8,%9}, {%0,%1,%2,%3};"
        : "+f"(c[0]), "+f"(c[1]), "+f"(c[2]), "+f"(c[3])
        : "r"(a[0]), "r"(a[1]), "r"(a[2]), "r"(a[3]), "r"(b0), "r"(b1));
}

// split one fp32 pair into bf16x2 hi and residual bf16x2 lo (x0 in low half)
__device__ __forceinline__ void cvt_pair(float x0, float x1,
                                         uint32_t& hi2, uint32_t& lo2) {
    asm("cvt.rn.bf16x2.f32 %0, %1, %2;" : "=r"(hi2) : "f"(x1), "f"(x0));
    float h0 = __uint_as_float(hi2 << 16);
    float h1 = __uint_as_float(hi2 & 0xffff0000u);
    float r0 = x0 - h0;
    float r1 = x1 - h1;
    asm("cvt.rn.bf16x2.f32 %0, %1, %2;" : "=r"(lo2) : "f"(r1), "f"(r0));
}

__device__ __forceinline__ void sts64(uint32_t addr, uint32_t a, uint32_t b) {
    asm volatile("st.shared.v2.b32 [%0], {%1, %2};"
                 :: "r"(addr), "r"(a), "r"(b) : "memory");
}

#define CP_ASYNC16(dst, src) \
    asm volatile("cp.async.cg.shared.global [%0], [%1], 16;" \
                 :: "r"(dst), "l"(src) : "memory")
#define CP_COMMIT() asm volatile("cp.async.commit_group;" ::: "memory")
#define CP_WAIT0()  asm volatile("cp.async.wait_group 0;" ::: "memory")

// ---------------------------------------------------------------------------
// Kernel 0: convert W fp32 -> bf16 hi/lo; zero g_hist
// ---------------------------------------------------------------------------
__global__ __launch_bounds__(256) void wconv_kernel(const float* __restrict__ W)
{
    int idx = blockIdx.x * 256 + threadIdx.x;      // 0 .. 32767
    float4 v = *(const float4*)(W + (size_t)idx * 4);
    uint32_t h0, l0, h1, l1;
    cvt_pair(v.x, v.y, h0, l0);
    cvt_pair(v.z, v.w, h1, l1);
    ((uint2*)g_Whi)[idx] = make_uint2(h0, h1);
    ((uint2*)g_Wlo)[idx] = make_uint2(l0, l1);
    if (idx < HBLK * NUM_EXPERTS) ((int*)g_hist)[idx] = 0;
}

// ---------------------------------------------------------------------------
// Kernel 1: HMMA split-bf16 gate GEMM, K-split x2 -> fp32 partials in gmem
// 256 threads, 8 warps (32x32 tiles), 2 CTAs/SM, ONE sync per chunk.
// (unchanged from the 59.9us winner)
// ---------------------------------------------------------------------------
__global__ __launch_bounds__(256, 2) void gate_kernel(
    const float* __restrict__ X)    // [N_TOKENS, MODEL_DIM]
{
    extern __shared__ char dsm[];

    const int tid  = threadIdx.x;
    const int lane = tid & 31;
    const int w    = tid >> 5;
    const int b    = blockIdx.x >> 1;
    const int ks   = blockIdx.x & 1;
    const int t0   = b * BT;
    const int kbase = ks * KHALF;

    uint32_t smem_raw = smem_to_u32(dsm);
    const uint32_t tile0 = (smem_raw + 1023) & ~1023u;

    const int wm = (w & 3) * 32;        // token rows
    const int wn = (w >> 2) * 32;       // expert cols

    const uint32_t a_row  = (uint32_t)(lane & 15);
    const uint32_t a_koff = (uint32_t)((lane >> 4) << 4);
    const uint32_t b_row  = (uint32_t)((lane & 7) + ((lane & 16) ? 8 : 0));
    const uint32_t b_koff = (uint32_t)((lane & 8) ? 16 : 0);

    float acc[2][4][4];
#pragma unroll
    for (int mi = 0; mi < 2; mi++)
#pragma unroll
        for (int j = 0; j < 4; j++)
#pragma unroll
            for (int q = 0; q < 4; q++) acc[mi][j][q] = 0.0f;

    float4 pa[8];
    const int brow = tid >> 3;
    const int bu   = tid & 7;

    // prologue: LDG A(0); cp.async B(0) into stage 0
    {
        const int k0 = kbase;
#pragma unroll
        for (int l = 0; l < 8; l++) {
            int i = l * 256 + tid;
            int row = i >> 4, q = i & 15;
            pa[l] = *(const float4*)(X + (size_t)(t0 + row) * MODEL_DIM + k0 + q * 4);
        }
#pragma unroll
        for (int l = 0; l < 2; l++) {
            int row = brow + l * 32;
            uint32_t off = SMEM_SWIZZLE_128B((uint32_t)(row * 128 + bu * 16));
            CP_ASYNC16(tile0 + B_HI_OFF + off,
                       (const char*)g_Whi + ((size_t)row * MODEL_DIM + k0) * 2 + bu * 16);
            CP_ASYNC16(tile0 + B_LO_OFF + off,
                       (const char*)g_Wlo + ((size_t)row * MODEL_DIM + k0) * 2 + bu * 16);
        }
        CP_COMMIT();
    }

    for (int c = 0; c < NCHUNK; c++) {
        const uint32_t sb  = tile0 + (uint32_t)(c & 1) * STAGE_BYTES;
        const uint32_t sbn = tile0 + (uint32_t)((c + 1) & 1) * STAGE_BYTES;

#pragma unroll
        for (int l = 0; l < 8; l++) {
            int i = l * 256 + tid;
            int row = i >> 4, q = i & 15;
            uint32_t h0, l0v, h1, l1v;
            cvt_pair(pa[l].x, pa[l].y, h0, l0v);
            cvt_pair(pa[l].z, pa[l].w, h1, l1v);
            uint32_t off = SMEM_SWIZZLE_128B((uint32_t)(row * 128 + q * 8));
            sts64(sb + A_HI_OFF + off, h0, h1);
            sts64(sb + A_LO_OFF + off, l0v, l1v);
        }

        if (c + 1 < NCHUNK) {
            const int k0 = kbase + (c + 1) * KC;
#pragma unroll
            for (int l = 0; l < 8; l++) {
                int i = l * 256 + tid;
                int row = i >> 4, q = i & 15;
                pa[l] = *(const float4*)(X + (size_t)(t0 + row) * MODEL_DIM + k0 + q * 4);
            }
        }

        CP_WAIT0();          // B(c) landed
        __syncthreads();     // single sync: A(c)/B(c) visible; all MMA(c-1) done

        if (c + 1 < NCHUNK) {
            const int k0 = kbase + (c + 1) * KC;
#pragma unroll
            for (int l = 0; l < 2; l++) {
                int row = brow + l * 32;
                uint32_t off = SMEM_SWIZZLE_128B((uint32_t)(row * 128 + bu * 16));
                CP_ASYNC16(sbn + B_HI_OFF + off,
                           (const char*)g_Whi + ((size_t)row * MODEL_DIM + k0) * 2 + bu * 16);
                CP_ASYNC16(sbn + B_LO_OFF + off,
                           (const char*)g_Wlo + ((size_t)row * MODEL_DIM + k0) * 2 + bu * 16);
            }
            CP_COMMIT();
        }

#pragma unroll
        for (int kk = 0; kk < 4; kk++) {
            uint32_t ah[2][4], al[2][4];
#pragma unroll
            for (int mi = 0; mi < 2; mi++) {
                uint32_t ro = (uint32_t)((wm + 16 * mi + a_row) * 128) + kk * 32 + a_koff;
                uint32_t sw = SMEM_SWIZZLE_128B(ro);
                ldm_x4(ah[mi], sb + A_HI_OFF + sw);
                ldm_x4(al[mi], sb + A_LO_OFF + sw);
            }
#pragma unroll
            for (int bi = 0; bi < 2; bi++) {
                uint32_t bhf[4], blf[4];
                uint32_t ro = (uint32_t)((wn + 16 * bi + b_row) * 128) + kk * 32 + b_koff;
                uint32_t sw = SMEM_SWIZZLE_128B(ro);
                ldm_x4(bhf, sb + B_HI_OFF + sw);
                ldm_x4(blf, sb + B_LO_OFF + sw);
#pragma unroll
                for (int mi = 0; mi < 2; mi++) {
#pragma unroll
                    for (int jj = 0; jj < 2; jj++) {
                        float* a = acc[mi][bi * 2 + jj];
                        mma16816(a, ah[mi], bhf[jj * 2], bhf[jj * 2 + 1]);
                        mma16816(a, ah[mi], blf[jj * 2], blf[jj * 2 + 1]);
                        mma16816(a, al[mi], bhf[jj * 2], bhf[jj * 2 + 1]);
                    }
                }
            }
        }
        // no trailing sync (two-stage safety via leading sync)
    }

    // Write fp32 partial logits to gmem
    float* gp = g_part[ks];
#pragma unroll
    for (int mi = 0; mi < 2; mi++) {
        int r0 = wm + 16 * mi + (lane >> 2);
#pragma unroll
        for (int j = 0; j < 4; j++) {
            int col = wn + j * 8 + 2 * (lane & 3);
            *(float2*)(gp + (size_t)(t0 + r0) * NUM_EXPERTS + col) =
                make_float2(acc[mi][j][0], acc[mi][j][1]);
            *(float2*)(gp + (size_t)(t0 + r0 + 8) * NUM_EXPERTS + col) =
                make_float2(acc[mi][j][2], acc[mi][j][3]);
        }
    }
}

// ---------------------------------------------------------------------------
// Kernel 2: warp-per-token: sum partials + softmax + top-2 + combine + hist
// (unchanged from the 59.9us winner)
// ---------------------------------------------------------------------------
__global__ __launch_bounds__(512) void finish_kernel(float* __restrict__ out)
{
    const int tid  = threadIdx.x;
    const int lane = tid & 31;
    const int w    = tid >> 5;
    const int token = blockIdx.x * 16 + w;

    const float* p0 = g_part[0] + (size_t)token * NUM_EXPERTS;
    const float* p1 = g_part[1] + (size_t)token * NUM_EXPERTS;
    float v0 = p0[lane]      + p1[lane];
    float v1 = p0[lane + 32] + p1[lane + 32];

    float m = fmaxf(v0, v1);
#pragma unroll
    for (int off = 16; off > 0; off >>= 1)
        m = fmaxf(m, __shfl_xor_sync(0xffffffffu, m, off));
    const float m1 = m;

    unsigned bb0 = __ballot_sync(0xffffffffu, v0 == m1);
    unsigned bb1 = __ballot_sync(0xffffffffu, v1 == m1);
    const int e1 = bb0 ? (__ffs(bb0) - 1) : (32 + __ffs(bb1) - 1);

    float u0 = (lane == e1)      ? -INFINITY : v0;
    float u1 = (lane + 32 == e1) ? -INFINITY : v1;
    float m2 = fmaxf(u0, u1);
#pragma unroll
    for (int off = 16; off > 0; off >>= 1)
        m2 = fmaxf(m2, __shfl_xor_sync(0xffffffffu, m2, off));
    bb0 = __ballot_sync(0xffffffffu, u0 == m2);
    bb1 = __ballot_sync(0xffffffffu, u1 == m2);
    const int e2 = bb0 ? (__ffs(bb0) - 1) : (32 + __ffs(bb1) - 1);

    float ex0 = expf(v0 - m1);
    float ex1 = expf(v1 - m1);
    float s = ex0 + ex1;
#pragma unroll
    for (int off = 16; off > 0; off >>= 1)
        s += __shfl_xor_sync(0xffffffffu, s, off);
    const float inv = 1.0f / s;

    out[OFF_PROBS + (size_t)token * NUM_EXPERTS + lane]      = ex0 * inv;
    out[OFF_PROBS + (size_t)token * NUM_EXPERTS + lane + 32] = ex1 * inv;

    if (lane == 0) {
        float p1v = inv;
        float p2v = expf(m2 - m1) * inv;
        float r  = expf(p2v - p1v);
        float c1 = 1.0f / (1.0f + r);
        float c2 = r * c1;

        int gi = 2 * token;
        g_flat_idx[gi]     = e1;
        g_flat_idx[gi + 1] = e2;
        out[OFF_CW + gi]     = c1;
        out[OFF_CW + gi + 1] = c2;

        atomicAdd(&g_hist[token >> 7][e1], 1);
        atomicAdd(&g_hist[token >> 7][e2], 1);
    }
}

// ---------------------------------------------------------------------------
// Kernel 3: FUSED prefix + stable scatter.
// 128 blocks x 256 threads. Each block independently reduces the full
// histogram with the segment trick (64 experts x 4 segments, chain 32),
// computing cnt[e] and the "chunks < b" partial in one pass, then does the
// match_any stable rank scatter for its own 256 slots.
// ---------------------------------------------------------------------------
__global__ __launch_bounds__(CHUNK) void scatter_kernel(float* __restrict__ out)
{
    __shared__ int sh[HBLK * NUM_EXPERTS];     // 32KB
    __shared__ int seg_cnt[4][NUM_EXPERTS];
    __shared__ int seg_off[4][NUM_EXPERTS];
    __shared__ int s_cnt[NUM_EXPERTS];
    __shared__ int s_off[NUM_EXPERTS];
    __shared__ int s_base[NUM_EXPERTS];
    __shared__ int whist[8][NUM_EXPERTS];

    const int tid  = threadIdx.x;
    const int lane = tid & 31;
    const int w    = tid >> 5;
    const int b    = blockIdx.x;
    const int gi   = b * CHUNK + tid;
    const int e    = tid & 63;
    const int s    = tid >> 6;                 // 0..3

    // stage full histogram (coalesced, 8 int4 per thread) + zero whist
    {
        const int4* src = (const int4*)g_hist;
        int4* dst = (int4*)sh;
#pragma unroll
        for (int l = 0; l < 8; l++) dst[l * 256 + tid] = src[l * 256 + tid];
    }
    if (tid < 8 * NUM_EXPERTS / 2) ((int2*)whist)[tid] = make_int2(0, 0);
    __syncthreads();

    // per-(expert, segment): total count and "< b" partial, one pass, chain 32
    {
        int cnt = 0, off = 0;
#pragma unroll 8
        for (int c = s * 32; c < s * 32 + 32; c++) {
            int h = sh[c * NUM_EXPERTS + e];
            cnt += h;
            off += (c < b) ? h : 0;
        }
        seg_cnt[s][e] = cnt;
        seg_off[s][e] = off;
    }
    __syncthreads();

    // combine segments (64 threads, chain 4)
    if (tid < NUM_EXPERTS) {
        int c0 = seg_cnt[0][tid], c1 = seg_cnt[1][tid],
            c2 = seg_cnt[2][tid], c3 = seg_cnt[3][tid];
        s_cnt[tid] = c0 + c1 + c2 + c3;
        s_off[tid] = seg_off[0][tid] + seg_off[1][tid]
                   + seg_off[2][tid] + seg_off[3][tid];
        if (b == 0) out[OFF_SPLITS + tid] = (float)(c0 + c1 + c2 + c3);
    }
    __syncthreads();
    if (tid == 0) {
        int base = 0;
#pragma unroll
        for (int i = 0; i < NUM_EXPERTS; i++) { s_base[i] = base; base += s_cnt[i]; }
    }

    // stable in-chunk rank via match_any + per-warp histograms
    const int me = g_flat_idx[gi];
    unsigned mask = __match_any_sync(0xffffffffu, me);
    int before = __popc(mask & ((1u << lane) - 1u));
    if (before == 0) whist[w][me] = __popc(mask);
    __syncthreads();

    int r = before;
#pragma unroll
    for (int ww = 0; ww < 8; ww++)
        if (ww < w) r += whist[ww][me];

    const int pos = s_base[me] + s_off[me] + r;
    out[OFF_TOKEN + pos] = (float)(gi >> 1);   // token index
    out[OFF_REV + gi]    = (float)pos;         // reversed ordering
}

// ---------------------------------------------------------------------------
extern "C" void kernel_launch(void* const* d_in, const int* in_sizes, int n_in,
                              void* d_out, int out_size)
{
    const float* X = (const float*)d_in[0];   // inputs [16384, 2048]
    const float* W = (const float*)d_in[1];   // wg_weight [64, 2048]
    float* out = (float*)d_out;

    cudaFuncSetAttribute(gate_kernel,
                         cudaFuncAttributeMaxDynamicSharedMemorySize, SMEM_DYN);

    wconv_kernel<<<128, 256>>>(W);
    gate_kernel<<<NGATE, 256, SMEM_DYN>>>(X);
    finish_kernel<<<N_TOKENS / 16, 512>>>(out);
    scatter_kernel<<<HBLK, CHUNK>>>(out);
}